// round 2
// baseline (speedup 1.0000x reference)
#include <cuda_runtime.h>
#include <cstdint>

// Problem constants
#define NSUP   25
#define NQ     400
#define SEQF   8
#define DIM    2048
#define DOUT   1024
#define KTOT   (3*DIM)          // 6144
#define TN     56               // C(8,3)
#define NWAY   5
#define SHOT   5
#define SACT   (SHOT*TN)        // 280 actual supports per class
#define CPAD   320              // padded to multiple of 64
#define QROWS  (NQ*TN)          // 22400

// combinations(range(8), 3) in itertools (lexicographic) order
__constant__ unsigned char TUP[TN][3] = {
  {0,1,2},{0,1,3},{0,1,4},{0,1,5},{0,1,6},{0,1,7},
  {0,2,3},{0,2,4},{0,2,5},{0,2,6},{0,2,7},
  {0,3,4},{0,3,5},{0,3,6},{0,3,7},
  {0,4,5},{0,4,6},{0,4,7},
  {0,5,6},{0,5,7},
  {0,6,7},
  {1,2,3},{1,2,4},{1,2,5},{1,2,6},{1,2,7},
  {1,3,4},{1,3,5},{1,3,6},{1,3,7},
  {1,4,5},{1,4,6},{1,4,7},
  {1,5,6},{1,5,7},
  {1,6,7},
  {2,3,4},{2,3,5},{2,3,6},{2,3,7},
  {2,4,5},{2,4,6},{2,4,7},
  {2,5,6},{2,5,7},
  {2,6,7},
  {3,4,5},{3,4,6},{3,4,7},
  {3,5,6},{3,5,7},
  {3,6,7},
  {4,5,6},{4,5,7},
  {4,6,7},
  {5,6,7}
};

// Scratch (allocation-free rule: __device__ globals)
__device__ float    g_Pq[(size_t)NQ*SEQF*3*DOUT];     // [3200][3][1024]  39.3 MB
__device__ float    g_Ps[(size_t)NSUP*SEQF*3*DOUT];   // [200][3][1024]    2.5 MB
__device__ float    g_qe[(size_t)QROWS*DOUT];         // [22400][1024]    91.8 MB
__device__ float    g_q2[QROWS];
__device__ float    g_se[(size_t)NWAY*CPAD*DOUT];     // grouped+padded    6.6 MB
__device__ float    g_s2[NWAY*CPAD];
__device__ unsigned g_minbits[NWAY*QROWS];            // per-(class,row) min dist^2 bits
__device__ int      g_clsidx[NWAY*SHOT];              // class -> support indices (stable)

// ---------------------------------------------------------------------------
// Stage 0: decode labels (auto-detect int32 vs int64) and build class map.
// Safe for both layouts: detection reads only the first NSUP int32 words,
// which is within bounds whether the buffer is 25*int32 or 25*int64.
// int64 little-endian [0..4] -> odd words all zero; int32 -> they are not.
// ---------------------------------------------------------------------------
__global__ void build_clsmap(const int* __restrict__ raw)
{
    if (threadIdx.x != 0 || blockIdx.x != 0) return;
    bool is64 = true;
    for (int i = 1; i < NSUP; i += 2)
        if (raw[i] != 0) { is64 = false; break; }
    if (is64) {
        // also require plausible low words in the int64 view
        for (int i = 0; i < NSUP; i += 2)
            if (raw[i] < 0 || raw[i] >= NWAY) { is64 = false; break; }
    }
    int cnt[NWAY];
    #pragma unroll
    for (int c = 0; c < NWAY; ++c) cnt[c] = 0;
    for (int i = 0; i < NSUP; ++i) {
        int lab = is64 ? raw[2*i] : raw[i];
        if (lab >= 0 && lab < NWAY && cnt[lab] < SHOT)
            g_clsidx[lab*SHOT + cnt[lab]++] = i;
    }
}

// ---------------------------------------------------------------------------
// Stage 1: per-frame partial embedding GEMM.
// P[m][j][o] = sum_d A[m][d] * W[o][j*2048 + d]
// A: [M, 2048] row-major (frames flattened). Tile 128x64, K-tile 16, 256 thr,
// 8x4 microtile.
// ---------------------------------------------------------------------------
template<bool GUARD, bool TO_Q>
__global__ __launch_bounds__(256) void partial_gemm(
    const float* __restrict__ A, int M, const float* __restrict__ W)
{
    float* __restrict__ P = TO_Q ? g_Pq : g_Ps;
    const int j     = blockIdx.z;
    const int mBase = blockIdx.x * 128;
    const int nBase = blockIdx.y * 64;

    __shared__ float As[16][132];   // [k][row]
    __shared__ float Bs[16][68];    // [k][col]

    const int tid = threadIdx.x;
    const int tx  = tid & 15;       // N dim, 4 cols each
    const int ty  = tid >> 4;       // M dim, 8 rows each

    float acc[8][4];
    #pragma unroll
    for (int i = 0; i < 8; ++i)
        #pragma unroll
        for (int jj = 0; jj < 4; ++jj) acc[i][jj] = 0.f;

    const int lr = tid >> 2;            // 0..63
    const int lk = (tid & 3) << 2;      // 0,4,8,12
    const float* wBase = W + (size_t)(nBase + lr) * KTOT + (size_t)j * DIM + lk;
    const int r0 = mBase + lr, r1 = r0 + 64;

    for (int k0 = 0; k0 < DIM; k0 += 16) {
        float4 a0 = make_float4(0.f,0.f,0.f,0.f);
        float4 a1 = make_float4(0.f,0.f,0.f,0.f);
        if (!GUARD || r0 < M) a0 = *(const float4*)(A + (size_t)r0*DIM + k0 + lk);
        if (!GUARD || r1 < M) a1 = *(const float4*)(A + (size_t)r1*DIM + k0 + lk);
        float4 w = *(const float4*)(wBase + k0);

        __syncthreads();
        As[lk+0][lr]    = a0.x; As[lk+1][lr]    = a0.y;
        As[lk+2][lr]    = a0.z; As[lk+3][lr]    = a0.w;
        As[lk+0][lr+64] = a1.x; As[lk+1][lr+64] = a1.y;
        As[lk+2][lr+64] = a1.z; As[lk+3][lr+64] = a1.w;
        Bs[lk+0][lr] = w.x; Bs[lk+1][lr] = w.y;
        Bs[lk+2][lr] = w.z; Bs[lk+3][lr] = w.w;
        __syncthreads();

        #pragma unroll
        for (int kt = 0; kt < 16; ++kt) {
            float a[8], bb[4];
            *(float4*)(a+0) = *(const float4*)&As[kt][ty*8];
            *(float4*)(a+4) = *(const float4*)&As[kt][ty*8+4];
            *(float4*)(bb)  = *(const float4*)&Bs[kt][tx*4];
            #pragma unroll
            for (int i = 0; i < 8; ++i)
                #pragma unroll
                for (int jj = 0; jj < 4; ++jj)
                    acc[i][jj] = fmaf(a[i], bb[jj], acc[i][jj]);
        }
    }

    #pragma unroll
    for (int i = 0; i < 8; ++i) {
        int row = mBase + ty*8 + i;
        if (GUARD && row >= M) break;
        float4 v = make_float4(acc[i][0], acc[i][1], acc[i][2], acc[i][3]);
        *(float4*)(P + ((size_t)row*3 + j)*DOUT + nBase + tx*4) = v;
    }
}

// ---------------------------------------------------------------------------
// Stage 2a: assemble qe rows (3-way partial sum + bias + relu) and q2 norms.
// One block per (q, tuple) row.
// ---------------------------------------------------------------------------
__device__ __forceinline__ float block_reduce_sum(float v) {
    #pragma unroll
    for (int off = 16; off > 0; off >>= 1)
        v += __shfl_xor_sync(0xffffffffu, v, off);
    __shared__ float ws[8];
    int lane = threadIdx.x & 31, wid = threadIdx.x >> 5;
    if (lane == 0) ws[wid] = v;
    __syncthreads();
    float t = 0.f;
    if (threadIdx.x == 0) {
        #pragma unroll
        for (int i = 0; i < 8; ++i) t += ws[i];
    }
    return t;
}

__global__ __launch_bounds__(256) void assemble_q(const float* __restrict__ bias)
{
    const int row = blockIdx.x;          // 0..22399
    const int q = row / TN, t = row % TN;
    const int f0 = TUP[t][0], f1 = TUP[t][1], f2 = TUP[t][2];
    const float* p0 = g_Pq + ((size_t)(q*SEQF + f0)*3 + 0)*DOUT;
    const float* p1 = g_Pq + ((size_t)(q*SEQF + f1)*3 + 1)*DOUT;
    const float* p2 = g_Pq + ((size_t)(q*SEQF + f2)*3 + 2)*DOUT;
    float* dst = g_qe + (size_t)row * DOUT;

    const int o = threadIdx.x * 4;
    float4 v0 = *(const float4*)(p0 + o);
    float4 v1 = *(const float4*)(p1 + o);
    float4 v2 = *(const float4*)(p2 + o);
    float4 vb = *(const float4*)(bias + o);
    float4 r;
    r.x = fmaxf(v0.x + v1.x + v2.x + vb.x, 0.f);
    r.y = fmaxf(v0.y + v1.y + v2.y + vb.y, 0.f);
    r.z = fmaxf(v0.z + v1.z + v2.z + vb.z, 0.f);
    r.w = fmaxf(v0.w + v1.w + v2.w + vb.w, 0.f);
    *(float4*)(dst + o) = r;
    float ss = r.x*r.x + r.y*r.y + r.z*r.z + r.w*r.w;
    float tot = block_reduce_sum(ss);
    if (threadIdx.x == 0) g_q2[row] = tot;
}

// ---------------------------------------------------------------------------
// Stage 2b: assemble se rows into class-grouped, padded layout + s2 norms.
// Layout row g = c*CPAD + (shotRank*56 + t); pad rows get se=0, s2=1e30.
// ---------------------------------------------------------------------------
__global__ __launch_bounds__(256) void assemble_s(const float* __restrict__ bias)
{
    const int g = blockIdx.x;            // 0..1599
    const int c = g / CPAD, slot = g % CPAD;
    float* dst = g_se + (size_t)g * DOUT;
    const int o = threadIdx.x * 4;

    if (slot >= SACT) {
        *(float4*)(dst + o) = make_float4(0.f, 0.f, 0.f, 0.f);
        if (threadIdx.x == 0) g_s2[g] = 1e30f;
        return;
    }
    const int shotIdx = slot / TN, t = slot % TN;
    const int n = g_clsidx[c*SHOT + shotIdx];
    const int f0 = TUP[t][0], f1 = TUP[t][1], f2 = TUP[t][2];
    const float* p0 = g_Ps + ((size_t)(n*SEQF + f0)*3 + 0)*DOUT;
    const float* p1 = g_Ps + ((size_t)(n*SEQF + f1)*3 + 1)*DOUT;
    const float* p2 = g_Ps + ((size_t)(n*SEQF + f2)*3 + 2)*DOUT;

    float4 v0 = *(const float4*)(p0 + o);
    float4 v1 = *(const float4*)(p1 + o);
    float4 v2 = *(const float4*)(p2 + o);
    float4 vb = *(const float4*)(bias + o);
    float4 r;
    r.x = fmaxf(v0.x + v1.x + v2.x + vb.x, 0.f);
    r.y = fmaxf(v0.y + v1.y + v2.y + vb.y, 0.f);
    r.z = fmaxf(v0.z + v1.z + v2.z + vb.z, 0.f);
    r.w = fmaxf(v0.w + v1.w + v2.w + vb.w, 0.f);
    *(float4*)(dst + o) = r;
    float ss = r.x*r.x + r.y*r.y + r.z*r.z + r.w*r.w;
    float tot = block_reduce_sum(ss);
    if (threadIdx.x == 0) g_s2[g] = tot;
}

// ---------------------------------------------------------------------------
// Stage 3 init: min buffer to +FLT_MAX bits.
// ---------------------------------------------------------------------------
__global__ void init_min()
{
    int i = blockIdx.x * blockDim.x + threadIdx.x;
    if (i < NWAY * QROWS) g_minbits[i] = 0x7F7FFFFFu;
}

// ---------------------------------------------------------------------------
// Stage 3: fused dots-GEMM + squared-distance + per-class min reduction.
// C-tile 128(M) x 64(N), K=1024. Grid (175, 5 n-tiles, 5 classes).
// dist2 = max(q2 + s2 - 2*dot, 0); min over supports via atomicMin on bits
// (valid: all values >= 0 so uint order == float order).
// ---------------------------------------------------------------------------
__global__ __launch_bounds__(256) void dist_gemm()
{
    const int c     = blockIdx.z;
    const int mBase = blockIdx.x * 128;
    const int nBase = blockIdx.y * 64;            // within padded class block

    __shared__ float As[16][132];
    __shared__ float Bs[16][68];
    __shared__ float redmin[128][17];

    const int tid = threadIdx.x;
    const int tx  = tid & 15;
    const int ty  = tid >> 4;

    float acc[8][4];
    #pragma unroll
    for (int i = 0; i < 8; ++i)
        #pragma unroll
        for (int jj = 0; jj < 4; ++jj) acc[i][jj] = 0.f;

    const int lr = tid >> 2;
    const int lk = (tid & 3) << 2;
    const float* aBase = g_qe + (size_t)(mBase + lr) * DOUT + lk;
    const float* bBase = g_se + (size_t)(c*CPAD + nBase + lr) * DOUT + lk;

    for (int k0 = 0; k0 < DOUT; k0 += 16) {
        float4 a0 = *(const float4*)(aBase + k0);
        float4 a1 = *(const float4*)(aBase + (size_t)64*DOUT + k0);
        float4 w  = *(const float4*)(bBase + k0);
        __syncthreads();
        As[lk+0][lr]    = a0.x; As[lk+1][lr]    = a0.y;
        As[lk+2][lr]    = a0.z; As[lk+3][lr]    = a0.w;
        As[lk+0][lr+64] = a1.x; As[lk+1][lr+64] = a1.y;
        As[lk+2][lr+64] = a1.z; As[lk+3][lr+64] = a1.w;
        Bs[lk+0][lr] = w.x; Bs[lk+1][lr] = w.y;
        Bs[lk+2][lr] = w.z; Bs[lk+3][lr] = w.w;
        __syncthreads();
        #pragma unroll
        for (int kt = 0; kt < 16; ++kt) {
            float a[8], bb[4];
            *(float4*)(a+0) = *(const float4*)&As[kt][ty*8];
            *(float4*)(a+4) = *(const float4*)&As[kt][ty*8+4];
            *(float4*)(bb)  = *(const float4*)&Bs[kt][tx*4];
            #pragma unroll
            for (int i = 0; i < 8; ++i)
                #pragma unroll
                for (int jj = 0; jj < 4; ++jj)
                    acc[i][jj] = fmaf(a[i], bb[jj], acc[i][jj]);
        }
    }

    // epilogue: dist^2, clamp, per-row min over the 64-col tile
    float s2c[4];
    #pragma unroll
    for (int jj = 0; jj < 4; ++jj)
        s2c[jj] = g_s2[c*CPAD + nBase + tx*4 + jj];

    #pragma unroll
    for (int i = 0; i < 8; ++i) {
        const int row = mBase + ty*8 + i;
        const float q2v = g_q2[row];
        float mn = 3.0e30f;
        #pragma unroll
        for (int jj = 0; jj < 4; ++jj) {
            float v = fmaxf(q2v + s2c[jj] - 2.f * acc[i][jj], 0.f);
            mn = fminf(mn, v);
        }
        redmin[ty*8 + i][tx] = mn;
    }
    __syncthreads();
    if (tid < 128) {
        float mn = redmin[tid][0];
        #pragma unroll
        for (int k = 1; k < 16; ++k) mn = fminf(mn, redmin[tid][k]);
        atomicMin(&g_minbits[c*QROWS + mBase + tid], __float_as_uint(mn));
    }
}

// ---------------------------------------------------------------------------
// Stage 4: logits[q][c] = -mean_t sqrt(min_dist2[c][q*56+t])
// ---------------------------------------------------------------------------
__global__ void finalize(float* __restrict__ out)
{
    int idx = blockIdx.x * blockDim.x + threadIdx.x;
    if (idx >= NQ * NWAY) return;
    int q = idx / NWAY, c = idx % NWAY;
    const unsigned* src = g_minbits + (size_t)c*QROWS + (size_t)q*TN;
    float s = 0.f;
    #pragma unroll 8
    for (int t = 0; t < TN; ++t)
        s += sqrtf(__uint_as_float(src[t]));
    out[q*NWAY + c] = -s * (1.0f / (float)TN);
}

// ---------------------------------------------------------------------------
extern "C" void kernel_launch(void* const* d_in, const int* in_sizes, int n_in,
                              void* d_out, int out_size)
{
    const float* support = (const float*)d_in[0];      // [25,8,2048]
    const int*   labraw  = (const int*)d_in[1];        // [25] int32 or int64
    const float* queries = (const float*)d_in[2];      // [400,8,2048]
    const float* W       = (const float*)d_in[3];      // [1024,6144]
    const float* bias    = (const float*)d_in[4];      // [1024]
    float*       out     = (float*)d_out;              // [400,5]
    (void)in_sizes; (void)n_in; (void)out_size;

    // Stage 0: class map from labels (dtype auto-detect)
    build_clsmap<<<1, 32>>>(labraw);

    // Stage 1: per-frame partial embeddings (7x FLOP reduction vs tuple GEMM)
    partial_gemm<false, true ><<<dim3(25, DOUT/64, 3), 256>>>(queries, NQ*SEQF, W);
    partial_gemm<true,  false><<<dim3(2,  DOUT/64, 3), 256>>>(support, NSUP*SEQF, W);

    // Stage 2: assemble tuple embeddings + norms
    assemble_q<<<QROWS, 256>>>(bias);
    assemble_s<<<NWAY*CPAD, 256>>>(bias);

    // Stage 3: fused distance GEMM with min-reduction
    init_min<<<(NWAY*QROWS + 255)/256, 256>>>();
    dist_gemm<<<dim3(QROWS/128, CPAD/64, NWAY), 256>>>();

    // Stage 4: mean over tuples, negate
    finalize<<<(NQ*NWAY + 255)/256, 256>>>(out);
}

// round 4
// speedup vs baseline: 2.6548x; 2.6548x over previous
#include <cuda_runtime.h>
#include <cuda_bf16.h>
#include <cstdint>

// ---------------- problem constants ----------------
#define NSUP 25
#define NQ 400
#define SEQF 8
#define DIM 2048
#define DOUT 1024
#define TN 56
#define NWAY 5
#define SHOT 5
#define SACT 280            // shot*Tn real supports per class
#define SPAD 384            // padded to 3 x 128 N-tiles
#define QROWS 22400         // 400*56
#define QPAD 22528          // 176*128
#define MFR 3200            // query frames
#define MFRS 3400           // + support frames
#define MPAD 3456           // 27*128

#define TILE_BYTES 16384                 // 128 rows x 128B (64 bf16)
#define SMEM_BYTES (8*TILE_BYTES)        // 2 stages x 4 tiles
#define SWZ(o) ((o) ^ (((o) >> 3) & 0x70))

// combinations(range(8),3), lexicographic
__constant__ unsigned char TUP[TN][3] = {
  {0,1,2},{0,1,3},{0,1,4},{0,1,5},{0,1,6},{0,1,7},
  {0,2,3},{0,2,4},{0,2,5},{0,2,6},{0,2,7},
  {0,3,4},{0,3,5},{0,3,6},{0,3,7},
  {0,4,5},{0,4,6},{0,4,7},
  {0,5,6},{0,5,7},{0,6,7},
  {1,2,3},{1,2,4},{1,2,5},{1,2,6},{1,2,7},
  {1,3,4},{1,3,5},{1,3,6},{1,3,7},
  {1,4,5},{1,4,6},{1,4,7},
  {1,5,6},{1,5,7},{1,6,7},
  {2,3,4},{2,3,5},{2,3,6},{2,3,7},
  {2,4,5},{2,4,6},{2,4,7},
  {2,5,6},{2,5,7},{2,6,7},
  {3,4,5},{3,4,6},{3,4,7},
  {3,5,6},{3,5,7},{3,6,7},
  {4,5,6},{4,5,7},{4,6,7},
  {5,6,7}
};

// ---------------- scratch (__device__ globals, allocation-free) ----------------
__device__ __align__(256) __nv_bfloat16 g_Ahi[(size_t)MPAD*DIM];
__device__ __align__(256) __nv_bfloat16 g_Alo[(size_t)MPAD*DIM];
__device__ __align__(256) __nv_bfloat16 g_Whi[(size_t)3*DOUT*DIM];
__device__ __align__(256) __nv_bfloat16 g_Wlo[(size_t)3*DOUT*DIM];
__device__ __align__(256) float         g_P[(size_t)MPAD*3*DOUT];
__device__ __align__(256) __nv_bfloat16 g_QEhi[(size_t)QPAD*DOUT];
__device__ __align__(256) __nv_bfloat16 g_QElo[(size_t)QPAD*DOUT];
__device__ __align__(256) float         g_q2[QPAD];
__device__ __align__(256) __nv_bfloat16 g_SEhi[(size_t)NWAY*SPAD*DOUT];
__device__ __align__(256) __nv_bfloat16 g_SElo[(size_t)NWAY*SPAD*DOUT];
__device__ __align__(256) float         g_s2[NWAY*SPAD];
__device__ __align__(256) unsigned      g_minbits[NWAY*QPAD];
__device__ int g_clsidx[NWAY*SHOT];

// ---------------- helpers ----------------
__device__ __forceinline__ uint32_t smem_u32(const void* p) {
    uint32_t a;
    asm("{ .reg .u64 t; cvta.to.shared.u64 t, %1; cvt.u32.u64 %0, t; }" : "=r"(a) : "l"(p));
    return a;
}
__device__ __forceinline__ void cp16(uint32_t s, const void* g) {
    asm volatile("cp.async.cg.shared.global [%0], [%1], 16;" :: "r"(s), "l"(g) : "memory");
}
#define LDSM4(r, addr) \
    asm volatile("ldmatrix.sync.aligned.m8n8.x4.shared.b16 {%0,%1,%2,%3}, [%4];" \
        : "=r"((r)[0]), "=r"((r)[1]), "=r"((r)[2]), "=r"((r)[3]) : "r"(addr))
#define MMA_BF16(c, a, b0, b1) \
    asm volatile("mma.sync.aligned.m16n8k16.row.col.f32.bf16.bf16.f32 " \
        "{%0,%1,%2,%3}, {%4,%5,%6,%7}, {%8,%9}, {%0,%1,%2,%3};" \
        : "+f"((c)[0]), "+f"((c)[1]), "+f"((c)[2]), "+f"((c)[3]) \
        : "r"((a)[0]), "r"((a)[1]), "r"((a)[2]), "r"((a)[3]), "r"(b0), "r"(b1))

// ---------------- shared MMA mainloop ----------------
// Tiles: [128 rows][64 bf16] SW128-swizzled. A rows = M, B rows = N, K-major.
__device__ __forceinline__ void load_tile(uint32_t sbase, const __nv_bfloat16* g,
                                          int stride, int kc, int tid) {
    const __nv_bfloat16* gp = g + (size_t)kc * 64;
    #pragma unroll
    for (int i = 0; i < 4; i++) {
        int idx = i * 256 + tid;
        int row = idx >> 3, seg = idx & 7;
        cp16(sbase + SWZ(row * 128 + seg * 16), gp + (size_t)row * stride + seg * 8);
    }
}

template<int KC>
__device__ __forceinline__ void mma_mainloop(
    const __nv_bfloat16* aHi, const __nv_bfloat16* aLo,
    const __nv_bfloat16* bHi, const __nv_bfloat16* bLo,
    int stride, char* smem, float acc[4][4][4])
{
    const uint32_t sb = smem_u32(smem);
    const int tid = threadIdx.x;
    const int l = tid & 31;
    const int wm = (tid >> 5) >> 2, wn = (tid >> 5) & 3;
    const __nv_bfloat16* tp[4] = { aHi, aLo, bHi, bLo };

    #pragma unroll
    for (int t = 0; t < 4; t++) load_tile(sb + t * TILE_BYTES, tp[t], stride, 0, tid);
    asm volatile("cp.async.commit_group;" ::: "memory");

    // ldmatrix lane address precompute (SW128: xor mask = (row&7)<<4, row&7
    // invariant under +16/+32/+64-row offsets)
    const uint32_t aRowB = (uint32_t)(wm * 64 + (l & 15)) * 128;
    const uint32_t aXm   = (uint32_t)(l & 7) << 4;
    const uint32_t aK    = ((l >> 4) & 1) * 16;
    const uint32_t bRowB = (uint32_t)(wn * 32 + (l & 7) + ((l >> 4) & 1) * 8) * 128;
    const uint32_t bXm   = (uint32_t)(l & 7) << 4;
    const uint32_t bK    = ((l >> 3) & 1) * 16;

    #pragma unroll 1
    for (int k = 0; k < KC; k++) {
        asm volatile("cp.async.wait_group 0;" ::: "memory");
        __syncthreads();
        if (k + 1 < KC) {
            const int s2 = (k + 1) & 1;
            #pragma unroll
            for (int t = 0; t < 4; t++)
                load_tile(sb + (s2 * 4 + t) * TILE_BYTES, tp[t], stride, k + 1, tid);
            asm volatile("cp.async.commit_group;" ::: "memory");
        }
        const uint32_t st = sb + (uint32_t)(k & 1) * 4 * TILE_BYTES;
        #pragma unroll
        for (int kk = 0; kk < 4; kk++) {
            uint32_t ah[4][4], al[4][4], bh[8], bl[8];
            const uint32_t ao = ((kk * 32 + aK) ^ aXm) + aRowB;
            const uint32_t bo = ((kk * 32 + bK) ^ bXm) + bRowB;
            #pragma unroll
            for (int mi = 0; mi < 4; mi++) LDSM4(ah[mi], st + ao + mi * 2048);
            #pragma unroll
            for (int mi = 0; mi < 4; mi++) LDSM4(al[mi], st + TILE_BYTES + ao + mi * 2048);
            LDSM4(bh + 0, st + 2 * TILE_BYTES + bo);
            LDSM4(bh + 4, st + 2 * TILE_BYTES + bo + 2048);
            LDSM4(bl + 0, st + 3 * TILE_BYTES + bo);
            LDSM4(bl + 4, st + 3 * TILE_BYTES + bo + 2048);
            #pragma unroll
            for (int mi = 0; mi < 4; mi++)
                #pragma unroll
                for (int ni = 0; ni < 4; ni++)
                    MMA_BF16(acc[mi][ni], ah[mi], bh[ni * 2], bh[ni * 2 + 1]);
            #pragma unroll
            for (int mi = 0; mi < 4; mi++)
                #pragma unroll
                for (int ni = 0; ni < 4; ni++)
                    MMA_BF16(acc[mi][ni], ah[mi], bl[ni * 2], bl[ni * 2 + 1]);
            #pragma unroll
            for (int mi = 0; mi < 4; mi++)
                #pragma unroll
                for (int ni = 0; ni < 4; ni++)
                    MMA_BF16(acc[mi][ni], al[mi], bh[ni * 2], bh[ni * 2 + 1]);
        }
    }
    __syncthreads();   // smem reusable after this
}

// ---------------- stage 0: label decode ----------------
__global__ void build_clsmap(const int* __restrict__ raw)
{
    if (threadIdx.x != 0 || blockIdx.x != 0) return;
    bool is64 = true;
    for (int i = 1; i < NSUP; i += 2) if (raw[i] != 0) { is64 = false; break; }
    if (is64) for (int i = 0; i < NSUP; i += 2) if (raw[i] < 0 || raw[i] >= NWAY) { is64 = false; break; }
    int cnt[NWAY];
    #pragma unroll
    for (int c = 0; c < NWAY; ++c) cnt[c] = 0;
    for (int i = 0; i < NSUP; ++i) {
        int lab = is64 ? raw[2 * i] : raw[i];
        if (lab >= 0 && lab < NWAY && cnt[lab] < SHOT)
            g_clsidx[lab * SHOT + cnt[lab]++] = i;
    }
}

// ---------------- conversion kernels ----------------
__device__ __forceinline__ void split_pack4(__nv_bfloat16* hi, __nv_bfloat16* lo, float4 r) {
    __nv_bfloat16 h0 = __float2bfloat16(r.x), h1 = __float2bfloat16(r.y),
                  h2 = __float2bfloat16(r.z), h3 = __float2bfloat16(r.w);
    __nv_bfloat16 l0 = __float2bfloat16(r.x - __bfloat162float(h0));
    __nv_bfloat16 l1 = __float2bfloat16(r.y - __bfloat162float(h1));
    __nv_bfloat16 l2 = __float2bfloat16(r.z - __bfloat162float(h2));
    __nv_bfloat16 l3 = __float2bfloat16(r.w - __bfloat162float(h3));
    uint2 ph, pl;
    ph.x = (uint32_t)__bfloat16_as_ushort(h0) | ((uint32_t)__bfloat16_as_ushort(h1) << 16);
    ph.y = (uint32_t)__bfloat16_as_ushort(h2) | ((uint32_t)__bfloat16_as_ushort(h3) << 16);
    pl.x = (uint32_t)__bfloat16_as_ushort(l0) | ((uint32_t)__bfloat16_as_ushort(l1) << 16);
    pl.y = (uint32_t)__bfloat16_as_ushort(l2) | ((uint32_t)__bfloat16_as_ushort(l3) << 16);
    *(uint2*)hi = ph; *(uint2*)lo = pl;
}

__global__ __launch_bounds__(256) void convsplit(const float* __restrict__ in,
                                                 size_t dstOff, int n4)
{
    int i = blockIdx.x * 256 + threadIdx.x;
    if (i >= n4) return;
    float4 x = ((const float4*)in)[i];
    split_pack4(g_Ahi + dstOff + (size_t)i * 4, g_Alo + dstOff + (size_t)i * 4, x);
}

__global__ __launch_bounds__(256) void zfillA()
{
    int i = blockIdx.x * 256 + threadIdx.x;
    int npad4 = (MPAD - MFRS) * DIM / 4;
    if (i >= npad4) return;
    size_t e = (size_t)MFRS * DIM + (size_t)i * 4;
    *(uint2*)(g_Ahi + e) = make_uint2(0, 0);
    *(uint2*)(g_Alo + e) = make_uint2(0, 0);
}

__global__ __launch_bounds__(256) void convW(const float* __restrict__ W)
{
    size_t i = (size_t)blockIdx.x * 256 + threadIdx.x;
    if (i >= (size_t)3 * DOUT * DIM / 4) return;
    size_t e = i * 4;
    int k = (int)(e & (DIM - 1));
    size_t r = e >> 11;
    int n = (int)(r & (DOUT - 1));
    int j = (int)(r >> 10);
    float4 x = *(const float4*)(W + (size_t)n * (3 * DIM) + (size_t)j * DIM + k);
    split_pack4(g_Whi + e, g_Wlo + e, x);
}

// ---------------- stage 1: partial-embedding GEMM (mma.sync bf16 3-term) ----------------
__global__ __launch_bounds__(256, 1) void gemm1()
{
    extern __shared__ char smem[];
    const int nBase = blockIdx.x * 128;
    const int j     = blockIdx.y;
    const int mBase = blockIdx.z * 128;
    float acc[4][4][4];
    #pragma unroll
    for (int a = 0; a < 4; a++)
        #pragma unroll
        for (int b = 0; b < 4; b++)
            #pragma unroll
            for (int c = 0; c < 4; c++) acc[a][b][c] = 0.f;

    mma_mainloop<DIM / 64>(
        g_Ahi + (size_t)mBase * DIM, g_Alo + (size_t)mBase * DIM,
        g_Whi + ((size_t)j * DOUT + nBase) * DIM, g_Wlo + ((size_t)j * DOUT + nBase) * DIM,
        DIM, smem, acc);

    const int tid = threadIdx.x, l = tid & 31;
    const int wm = (tid >> 5) >> 2, wn = (tid >> 5) & 3;
    #pragma unroll
    for (int mi = 0; mi < 4; mi++) {
        const int r0 = mBase + wm * 64 + mi * 16 + (l >> 2);
        #pragma unroll
        for (int ni = 0; ni < 4; ni++) {
            const int col = nBase + wn * 32 + ni * 8 + (l & 3) * 2;
            float2 v0 = make_float2(acc[mi][ni][0], acc[mi][ni][1]);
            float2 v1 = make_float2(acc[mi][ni][2], acc[mi][ni][3]);
            *(float2*)(g_P + ((size_t)r0 * 3 + j) * DOUT + col) = v0;
            *(float2*)(g_P + ((size_t)(r0 + 8) * 3 + j) * DOUT + col) = v1;
        }
    }
}

// ---------------- stage 2: assembly + norms + bf16 split ----------------
__device__ __forceinline__ float block_reduce_sum(float v) {
    #pragma unroll
    for (int off = 16; off > 0; off >>= 1) v += __shfl_xor_sync(0xffffffffu, v, off);
    __shared__ float ws[8];
    int lane = threadIdx.x & 31, w = threadIdx.x >> 5;
    if (lane == 0) ws[w] = v;
    __syncthreads();
    float t = 0.f;
    if (threadIdx.x == 0) {
        #pragma unroll
        for (int i = 0; i < 8; ++i) t += ws[i];
    }
    return t;
}

__global__ __launch_bounds__(256) void assemble_q(const float* __restrict__ bias)
{
    const int row = blockIdx.x;
    const int o = threadIdx.x * 4;
    __nv_bfloat16* hi = g_QEhi + (size_t)row * DOUT + o;
    __nv_bfloat16* lo = g_QElo + (size_t)row * DOUT + o;
    if (row >= QROWS) {
        *(uint2*)hi = make_uint2(0, 0);
        *(uint2*)lo = make_uint2(0, 0);
        if (threadIdx.x == 0) g_q2[row] = 0.f;
        return;
    }
    const int q = row / TN, t = row % TN;
    const int f0 = TUP[t][0], f1 = TUP[t][1], f2 = TUP[t][2];
    const float* p0 = g_P + ((size_t)(q * SEQF + f0) * 3 + 0) * DOUT + o;
    const float* p1 = g_P + ((size_t)(q * SEQF + f1) * 3 + 1) * DOUT + o;
    const float* p2 = g_P + ((size_t)(q * SEQF + f2) * 3 + 2) * DOUT + o;
    float4 v0 = *(const float4*)p0, v1 = *(const float4*)p1, v2 = *(const float4*)p2;
    float4 vb = *(const float4*)(bias + o);
    float4 r;
    r.x = fmaxf(v0.x + v1.x + v2.x + vb.x, 0.f);
    r.y = fmaxf(v0.y + v1.y + v2.y + vb.y, 0.f);
    r.z = fmaxf(v0.z + v1.z + v2.z + vb.z, 0.f);
    r.w = fmaxf(v0.w + v1.w + v2.w + vb.w, 0.f);
    split_pack4(hi, lo, r);
    float tot = block_reduce_sum(r.x * r.x + r.y * r.y + r.z * r.z + r.w * r.w);
    if (threadIdx.x == 0) g_q2[row] = tot;
}

__global__ __launch_bounds__(256) void assemble_s(const float* __restrict__ bias)
{
    const int g = blockIdx.x;
    const int c = g / SPAD, slot = g % SPAD;
    const int o = threadIdx.x * 4;
    __nv_bfloat16* hi = g_SEhi + (size_t)g * DOUT + o;
    __nv_bfloat16* lo = g_SElo + (size_t)g * DOUT + o;
    if (slot >= SACT) {
        *(uint2*)hi = make_uint2(0, 0);
        *(uint2*)lo = make_uint2(0, 0);
        if (threadIdx.x == 0) g_s2[g] = 1e30f;
        return;
    }
    const int n = g_clsidx[c * SHOT + slot / TN];
    const int t = slot % TN;
    const int f0 = TUP[t][0], f1 = TUP[t][1], f2 = TUP[t][2];
    const float* p0 = g_P + ((size_t)(MFR + n * SEQF + f0) * 3 + 0) * DOUT + o;
    const float* p1 = g_P + ((size_t)(MFR + n * SEQF + f1) * 3 + 1) * DOUT + o;
    const float* p2 = g_P + ((size_t)(MFR + n * SEQF + f2) * 3 + 2) * DOUT + o;
    float4 v0 = *(const float4*)p0, v1 = *(const float4*)p1, v2 = *(const float4*)p2;
    float4 vb = *(const float4*)(bias + o);
    float4 r;
    r.x = fmaxf(v0.x + v1.x + v2.x + vb.x, 0.f);
    r.y = fmaxf(v0.y + v1.y + v2.y + vb.y, 0.f);
    r.z = fmaxf(v0.z + v1.z + v2.z + vb.z, 0.f);
    r.w = fmaxf(v0.w + v1.w + v2.w + vb.w, 0.f);
    split_pack4(hi, lo, r);
    float tot = block_reduce_sum(r.x * r.x + r.y * r.y + r.z * r.z + r.w * r.w);
    if (threadIdx.x == 0) g_s2[g] = tot;
}

// ---------------- stage 3: fused distance GEMM + per-class min ----------------
__global__ void init_min()
{
    int i = blockIdx.x * blockDim.x + threadIdx.x;
    if (i < NWAY * QPAD) g_minbits[i] = 0x7F7FFFFFu;
}

__global__ __launch_bounds__(256, 1) void gemm3()
{
    extern __shared__ char smem[];
    __shared__ float s2s[128];
    __shared__ float rowmin[128][4];
    const int nBase = blockIdx.x * 128;
    const int c     = blockIdx.y;
    const int mBase = blockIdx.z * 128;
    const int tid = threadIdx.x, l = tid & 31;
    const int wm = (tid >> 5) >> 2, wn = (tid >> 5) & 3;

    if (tid < 128) s2s[tid] = g_s2[c * SPAD + nBase + tid];

    float acc[4][4][4];
    #pragma unroll
    for (int a = 0; a < 4; a++)
        #pragma unroll
        for (int b = 0; b < 4; b++)
            #pragma unroll
            for (int d = 0; d < 4; d++) acc[a][b][d] = 0.f;

    mma_mainloop<DOUT / 64>(
        g_QEhi + (size_t)mBase * DOUT, g_QElo + (size_t)mBase * DOUT,
        g_SEhi + ((size_t)c * SPAD + nBase) * DOUT, g_SElo + ((size_t)c * SPAD + nBase) * DOUT,
        DOUT, smem, acc);

    // per-thread: v = s2[col] - 2*dot; min over this thread's 8 cols per row
    float mn0[4], mn1[4];
    #pragma unroll
    for (int mi = 0; mi < 4; mi++) { mn0[mi] = 3.0e38f; mn1[mi] = 3.0e38f; }
    #pragma unroll
    for (int mi = 0; mi < 4; mi++)
        #pragma unroll
        for (int ni = 0; ni < 4; ni++) {
            const int col = wn * 32 + ni * 8 + (l & 3) * 2;
            float sa = s2s[col], sb = s2s[col + 1];
            mn0[mi] = fminf(mn0[mi], fminf(fmaf(-2.f, acc[mi][ni][0], sa),
                                           fmaf(-2.f, acc[mi][ni][1], sb)));
            mn1[mi] = fminf(mn1[mi], fminf(fmaf(-2.f, acc[mi][ni][2], sa),
                                           fmaf(-2.f, acc[mi][ni][3], sb)));
        }
    // reduce across the 4 lanes of each quad (same rows)
    #pragma unroll
    for (int mi = 0; mi < 4; mi++) {
        mn0[mi] = fminf(mn0[mi], __shfl_xor_sync(0xffffffffu, mn0[mi], 1));
        mn0[mi] = fminf(mn0[mi], __shfl_xor_sync(0xffffffffu, mn0[mi], 2));
        mn1[mi] = fminf(mn1[mi], __shfl_xor_sync(0xffffffffu, mn1[mi], 1));
        mn1[mi] = fminf(mn1[mi], __shfl_xor_sync(0xffffffffu, mn1[mi], 2));
    }
    if ((l & 3) == 0) {
        #pragma unroll
        for (int mi = 0; mi < 4; mi++) {
            rowmin[wm * 64 + mi * 16 + (l >> 2)][wn] = mn0[mi];
            rowmin[wm * 64 + mi * 16 + 8 + (l >> 2)][wn] = mn1[mi];
        }
    }
    __syncthreads();
    if (tid < 128) {
        float m = fminf(fminf(rowmin[tid][0], rowmin[tid][1]),
                        fminf(rowmin[tid][2], rowmin[tid][3]));
        float v = fmaxf(g_q2[mBase + tid] + m, 0.f);
        atomicMin(&g_minbits[c * QPAD + mBase + tid], __float_as_uint(v));
    }
}

// ---------------- stage 4: finalize ----------------
__global__ void finalize(float* __restrict__ out)
{
    int idx = blockIdx.x * blockDim.x + threadIdx.x;
    if (idx >= NQ * NWAY) return;
    int q = idx / NWAY, c = idx % NWAY;
    const unsigned* src = g_minbits + (size_t)c * QPAD + (size_t)q * TN;
    float s = 0.f;
    #pragma unroll 8
    for (int t = 0; t < TN; ++t) s += sqrtf(__uint_as_float(src[t]));
    out[q * NWAY + c] = -s * (1.0f / (float)TN);
}

// ---------------- launch ----------------
extern "C" void kernel_launch(void* const* d_in, const int* in_sizes, int n_in,
                              void* d_out, int out_size)
{
    const float* support = (const float*)d_in[0];      // [25,8,2048]
    const int*   labraw  = (const int*)d_in[1];        // [25] int32/int64
    const float* queries = (const float*)d_in[2];      // [400,8,2048]
    const float* W       = (const float*)d_in[3];      // [1024,6144]
    const float* bias    = (const float*)d_in[4];      // [1024]
    float*       out     = (float*)d_out;              // [400,5]
    (void)in_sizes; (void)n_in; (void)out_size;

    cudaFuncSetAttribute(gemm1, cudaFuncAttributeMaxDynamicSharedMemorySize, SMEM_BYTES);
    cudaFuncSetAttribute(gemm3, cudaFuncAttributeMaxDynamicSharedMemorySize, SMEM_BYTES);

    build_clsmap<<<1, 32>>>(labraw);

    convsplit<<<(MFR * DIM / 4 + 255) / 256, 256>>>(queries, 0, MFR * DIM / 4);
    convsplit<<<(NSUP * SEQF * DIM / 4 + 255) / 256, 256>>>(
        support, (size_t)MFR * DIM, NSUP * SEQF * DIM / 4);
    zfillA<<<((MPAD - MFRS) * DIM / 4 + 255) / 256, 256>>>();
    convW<<<(3 * DOUT * DIM / 4 + 255) / 256, 256>>>(W);

    gemm1<<<dim3(DOUT / 128, 3, MPAD / 128), 256, SMEM_BYTES>>>();

    assemble_q<<<QPAD, 256>>>(bias);
    assemble_s<<<NWAY * SPAD, 256>>>(bias);

    init_min<<<(NWAY * QPAD + 255) / 256, 256>>>();
    gemm3<<<dim3(SPAD / 128, NWAY, QPAD / 128), 256, SMEM_BYTES>>>();

    finalize<<<(NQ * NWAY + 255) / 256, 256>>>(out);
}

// round 5
// speedup vs baseline: 7.0623x; 2.6601x over previous
#include <cuda_runtime.h>
#include <cuda_fp16.h>
#include <cstdint>

// ---------------- problem constants ----------------
#define NSUP 25
#define NQ 400
#define SEQF 8
#define DIM 2048
#define DOUT 1024
#define TN 56
#define NWAY 5
#define SHOT 5
#define SACT 280            // shot*Tn real supports per class
#define SPACK 1408          // 5*280 packed + 8 pad = 11 x 128 tiles
#define QROWS 22400         // 400*56
#define QPAD 22528          // 176*128
#define MFR 3200            // query frames
#define MFRS 3400           // + support frames
#define MPAD 3456           // 27*128

#define TILE_BYTES 16384                 // 128 rows x 128B (64 fp16)
#define STAGE_BYTES (4*TILE_BYTES)       // A0,A1,B0,B1 (K-chunk 128)
#define SMEM_BYTES (2*STAGE_BYTES)       // 128 KB
#define SWZ(o) ((o) ^ (((o) >> 3) & 0x70))

// combinations(range(8),3), lexicographic
__constant__ unsigned char TUP[TN][3] = {
  {0,1,2},{0,1,3},{0,1,4},{0,1,5},{0,1,6},{0,1,7},
  {0,2,3},{0,2,4},{0,2,5},{0,2,6},{0,2,7},
  {0,3,4},{0,3,5},{0,3,6},{0,3,7},
  {0,4,5},{0,4,6},{0,4,7},
  {0,5,6},{0,5,7},{0,6,7},
  {1,2,3},{1,2,4},{1,2,5},{1,2,6},{1,2,7},
  {1,3,4},{1,3,5},{1,3,6},{1,3,7},
  {1,4,5},{1,4,6},{1,4,7},
  {1,5,6},{1,5,7},{1,6,7},
  {2,3,4},{2,3,5},{2,3,6},{2,3,7},
  {2,4,5},{2,4,6},{2,4,7},
  {2,5,6},{2,5,7},{2,6,7},
  {3,4,5},{3,4,6},{3,4,7},
  {3,5,6},{3,5,7},{3,6,7},
  {4,5,6},{4,5,7},{4,6,7},
  {5,6,7}
};

// ---------------- scratch (__device__ globals) ----------------
__device__ __align__(256) __half g_Ah[(size_t)MPAD*DIM];          // frames fp16
__device__ __align__(256) __half g_Wh[(size_t)3*DOUT*DIM];        // W rearranged fp16
__device__ __align__(256) float  g_P[(size_t)MPAD*3*DOUT];        // partial embeddings fp32
__device__ __align__(256) __half g_QE[(size_t)QPAD*DOUT];         // query tuple emb fp16
__device__ __align__(256) float  g_q2[QPAD];
__device__ __align__(256) __half g_SE[(size_t)SPACK*DOUT];        // packed support emb fp16
__device__ __align__(256) float  g_s2[SPACK];
__device__ __align__(256) unsigned g_minbits[NWAY*QPAD];
__device__ int g_clsidx[NWAY*SHOT];

// ---------------- helpers ----------------
__device__ __forceinline__ uint32_t smem_u32(const void* p) {
    uint32_t a;
    asm("{ .reg .u64 t; cvta.to.shared.u64 t, %1; cvt.u32.u64 %0, t; }" : "=r"(a) : "l"(p));
    return a;
}
__device__ __forceinline__ void cp16(uint32_t s, const void* g) {
    asm volatile("cp.async.cg.shared.global [%0], [%1], 16;" :: "r"(s), "l"(g) : "memory");
}
#define LDSM4(r, addr) \
    asm volatile("ldmatrix.sync.aligned.m8n8.x4.shared.b16 {%0,%1,%2,%3}, [%4];" \
        : "=r"((r)[0]), "=r"((r)[1]), "=r"((r)[2]), "=r"((r)[3]) : "r"(addr))
#define MMA_F16(c, a, b0, b1) \
    asm volatile("mma.sync.aligned.m16n8k16.row.col.f32.f16.f16.f32 " \
        "{%0,%1,%2,%3}, {%4,%5,%6,%7}, {%8,%9}, {%0,%1,%2,%3};" \
        : "+f"((c)[0]), "+f"((c)[1]), "+f"((c)[2]), "+f"((c)[3]) \
        : "r"((a)[0]), "r"((a)[1]), "r"((a)[2]), "r"((a)[3]), "r"(b0), "r"(b1))

// ---------------- shared MMA mainloop (single fp16, K-chunk 128) ----------------
__device__ __forceinline__ void load_tile(uint32_t sbase, const __half* g,
                                          int stride, int ksub, int tid) {
    const __half* gp = g + (size_t)ksub * 64;
    #pragma unroll
    for (int i = 0; i < 4; i++) {
        int idx = i * 256 + tid;
        int row = idx >> 3, seg = idx & 7;
        cp16(sbase + SWZ(row * 128 + seg * 16), gp + (size_t)row * stride + seg * 8);
    }
}
__device__ __forceinline__ void load_stage(uint32_t sbase, const __half* A, const __half* B,
                                           int stride, int chunk, int tid) {
    load_tile(sbase + 0 * TILE_BYTES, A, stride, chunk * 2 + 0, tid);
    load_tile(sbase + 1 * TILE_BYTES, A, stride, chunk * 2 + 1, tid);
    load_tile(sbase + 2 * TILE_BYTES, B, stride, chunk * 2 + 0, tid);
    load_tile(sbase + 3 * TILE_BYTES, B, stride, chunk * 2 + 1, tid);
}

template<int KC>   // number of 128-wide K chunks
__device__ __forceinline__ void mma_mainloop(
    const __half* A, const __half* B, int stride, char* smem, float acc[4][4][4])
{
    const uint32_t sb = smem_u32(smem);
    const int tid = threadIdx.x;
    const int l = tid & 31;

    load_stage(sb, A, B, stride, 0, tid);
    asm volatile("cp.async.commit_group;" ::: "memory");

    // ldmatrix lane addressing (SW128: xor mask = (lane&7)<<4)
    const int wm = (tid >> 5) >> 2, wn = (tid >> 5) & 3;
    const uint32_t aRowB = (uint32_t)(wm * 64 + (l & 15)) * 128;
    const uint32_t aXm   = (uint32_t)(l & 7) << 4;
    const uint32_t aK    = ((l >> 4) & 1) * 16;
    const uint32_t bRowB = (uint32_t)(wn * 32 + (l & 7) + ((l >> 4) & 1) * 8) * 128;
    const uint32_t bXm   = (uint32_t)(l & 7) << 4;
    const uint32_t bK    = ((l >> 3) & 1) * 16;

    #pragma unroll 1
    for (int k = 0; k < KC; k++) {
        asm volatile("cp.async.wait_group 0;" ::: "memory");
        __syncthreads();
        if (k + 1 < KC) {
            load_stage(sb + (uint32_t)((k + 1) & 1) * STAGE_BYTES, A, B, stride, k + 1, tid);
            asm volatile("cp.async.commit_group;" ::: "memory");
        }
        const uint32_t st = sb + (uint32_t)(k & 1) * STAGE_BYTES;
        #pragma unroll
        for (int ks = 0; ks < 2; ks++) {
            const uint32_t tA = st + (uint32_t)ks * TILE_BYTES;
            const uint32_t tB = st + 2 * TILE_BYTES + (uint32_t)ks * TILE_BYTES;
            #pragma unroll
            for (int kk = 0; kk < 4; kk++) {
                uint32_t a[4][4], b[8];
                const uint32_t ao = ((kk * 32 + aK) ^ aXm) + aRowB;
                const uint32_t bo = ((kk * 32 + bK) ^ bXm) + bRowB;
                #pragma unroll
                for (int mi = 0; mi < 4; mi++) LDSM4(a[mi], tA + ao + mi * 2048);
                LDSM4(b + 0, tB + bo);
                LDSM4(b + 4, tB + bo + 2048);
                #pragma unroll
                for (int mi = 0; mi < 4; mi++)
                    #pragma unroll
                    for (int ni = 0; ni < 4; ni++)
                        MMA_F16(acc[mi][ni], a[mi], b[ni * 2], b[ni * 2 + 1]);
            }
        }
    }
    __syncthreads();   // smem reusable after this
}

// ---------------- stage 0: label decode ----------------
__global__ void build_clsmap(const int* __restrict__ raw)
{
    if (threadIdx.x != 0 || blockIdx.x != 0) return;
    bool is64 = true;
    for (int i = 1; i < NSUP; i += 2) if (raw[i] != 0) { is64 = false; break; }
    if (is64) for (int i = 0; i < NSUP; i += 2) if (raw[i] < 0 || raw[i] >= NWAY) { is64 = false; break; }
    int cnt[NWAY];
    #pragma unroll
    for (int c = 0; c < NWAY; ++c) cnt[c] = 0;
    for (int i = 0; i < NSUP; ++i) {
        int lab = is64 ? raw[2 * i] : raw[i];
        if (lab >= 0 && lab < NWAY && cnt[lab] < SHOT)
            g_clsidx[lab * SHOT + cnt[lab]++] = i;
    }
}

// ---------------- conversion kernels ----------------
__device__ __forceinline__ uint2 pack_half4(float4 r) {
    __half h0 = __float2half_rn(r.x), h1 = __float2half_rn(r.y),
           h2 = __float2half_rn(r.z), h3 = __float2half_rn(r.w);
    uint2 p;
    p.x = (uint32_t)__half_as_ushort(h0) | ((uint32_t)__half_as_ushort(h1) << 16);
    p.y = (uint32_t)__half_as_ushort(h2) | ((uint32_t)__half_as_ushort(h3) << 16);
    return p;
}
__device__ __forceinline__ float sumsq_half4(uint2 p) {
    float f0 = __half2float(__ushort_as_half((unsigned short)(p.x & 0xffff)));
    float f1 = __half2float(__ushort_as_half((unsigned short)(p.x >> 16)));
    float f2 = __half2float(__ushort_as_half((unsigned short)(p.y & 0xffff)));
    float f3 = __half2float(__ushort_as_half((unsigned short)(p.y >> 16)));
    return f0 * f0 + f1 * f1 + f2 * f2 + f3 * f3;
}

__global__ __launch_bounds__(256) void convhalf(const float* __restrict__ in,
                                                size_t dstOff, int n4)
{
    int i = blockIdx.x * 256 + threadIdx.x;
    if (i >= n4) return;
    float4 x = ((const float4*)in)[i];
    *(uint2*)(g_Ah + dstOff + (size_t)i * 4) = pack_half4(x);
}

__global__ __launch_bounds__(256) void zfillA()
{
    int i = blockIdx.x * 256 + threadIdx.x;
    int npad4 = (MPAD - MFRS) * DIM / 4;
    if (i >= npad4) return;
    *(uint2*)(g_Ah + (size_t)MFRS * DIM + (size_t)i * 4) = make_uint2(0, 0);
}

__global__ __launch_bounds__(256) void convW(const float* __restrict__ W)
{
    size_t i = (size_t)blockIdx.x * 256 + threadIdx.x;
    if (i >= (size_t)3 * DOUT * DIM / 4) return;
    size_t e = i * 4;
    int k = (int)(e & (DIM - 1));
    size_t r = e >> 11;
    int n = (int)(r & (DOUT - 1));
    int j = (int)(r >> 10);
    float4 x = *(const float4*)(W + (size_t)n * (3 * DIM) + (size_t)j * DIM + k);
    *(uint2*)(g_Wh + e) = pack_half4(x);
}

// ---------------- stage 1: partial-embedding GEMM ----------------
__global__ __launch_bounds__(256, 1) void gemm1()
{
    extern __shared__ char smem[];
    const int nBase = blockIdx.x * 128;
    const int j     = blockIdx.y;
    const int mBase = blockIdx.z * 128;
    float acc[4][4][4];
    #pragma unroll
    for (int a = 0; a < 4; a++)
        #pragma unroll
        for (int b = 0; b < 4; b++)
            #pragma unroll
            for (int c = 0; c < 4; c++) acc[a][b][c] = 0.f;

    mma_mainloop<DIM / 128>(
        g_Ah + (size_t)mBase * DIM,
        g_Wh + ((size_t)j * DOUT + nBase) * DIM,
        DIM, smem, acc);

    const int tid = threadIdx.x, l = tid & 31;
    const int wm = (tid >> 5) >> 2, wn = (tid >> 5) & 3;
    #pragma unroll
    for (int mi = 0; mi < 4; mi++) {
        const int r0 = mBase + wm * 64 + mi * 16 + (l >> 2);
        #pragma unroll
        for (int ni = 0; ni < 4; ni++) {
            const int col = nBase + wn * 32 + ni * 8 + (l & 3) * 2;
            *(float2*)(g_P + ((size_t)r0 * 3 + j) * DOUT + col) =
                make_float2(acc[mi][ni][0], acc[mi][ni][1]);
            *(float2*)(g_P + ((size_t)(r0 + 8) * 3 + j) * DOUT + col) =
                make_float2(acc[mi][ni][2], acc[mi][ni][3]);
        }
    }
}

// ---------------- stage 2: assembly + rounded norms ----------------
__device__ __forceinline__ float block_reduce_sum(float v) {
    #pragma unroll
    for (int off = 16; off > 0; off >>= 1) v += __shfl_xor_sync(0xffffffffu, v, off);
    __shared__ float ws[8];
    int lane = threadIdx.x & 31, w = threadIdx.x >> 5;
    if (lane == 0) ws[w] = v;
    __syncthreads();
    float t = 0.f;
    if (threadIdx.x == 0) {
        #pragma unroll
        for (int i = 0; i < 8; ++i) t += ws[i];
    }
    return t;
}

__global__ __launch_bounds__(256) void assemble_q(const float* __restrict__ bias)
{
    const int row = blockIdx.x;                  // 0..QPAD-1
    const int o = threadIdx.x * 4;
    __half* dst = g_QE + (size_t)row * DOUT + o;
    if (row >= QROWS) {
        *(uint2*)dst = make_uint2(0, 0);
        if (threadIdx.x == 0) g_q2[row] = 0.f;
        return;
    }
    const int q = row / TN, t = row % TN;
    const int f0 = TUP[t][0], f1 = TUP[t][1], f2 = TUP[t][2];
    const float* p0 = g_P + ((size_t)(q * SEQF + f0) * 3 + 0) * DOUT + o;
    const float* p1 = g_P + ((size_t)(q * SEQF + f1) * 3 + 1) * DOUT + o;
    const float* p2 = g_P + ((size_t)(q * SEQF + f2) * 3 + 2) * DOUT + o;
    float4 v0 = *(const float4*)p0, v1 = *(const float4*)p1, v2 = *(const float4*)p2;
    float4 vb = *(const float4*)(bias + o);
    float4 r;
    r.x = fmaxf(v0.x + v1.x + v2.x + vb.x, 0.f);
    r.y = fmaxf(v0.y + v1.y + v2.y + vb.y, 0.f);
    r.z = fmaxf(v0.z + v1.z + v2.z + vb.z, 0.f);
    r.w = fmaxf(v0.w + v1.w + v2.w + vb.w, 0.f);
    uint2 p = pack_half4(r);
    *(uint2*)dst = p;
    // q2 from the ROUNDED values (consistency with the fp16 dot)
    float tot = block_reduce_sum(sumsq_half4(p));
    if (threadIdx.x == 0) g_q2[row] = tot;
}

__global__ __launch_bounds__(256) void assemble_s(const float* __restrict__ bias)
{
    const int pcol = blockIdx.x;                 // 0..SPACK-1 packed col
    const int o = threadIdx.x * 4;
    __half* dst = g_SE + (size_t)pcol * DOUT + o;
    if (pcol >= NWAY * SACT) {
        *(uint2*)dst = make_uint2(0, 0);
        if (threadIdx.x == 0) g_s2[pcol] = 1e30f;
        return;
    }
    const int c = pcol / SACT, slot = pcol % SACT;
    const int n = g_clsidx[c * SHOT + slot / TN];
    const int t = slot % TN;
    const int f0 = TUP[t][0], f1 = TUP[t][1], f2 = TUP[t][2];
    const float* p0 = g_P + ((size_t)(MFR + n * SEQF + f0) * 3 + 0) * DOUT + o;
    const float* p1 = g_P + ((size_t)(MFR + n * SEQF + f1) * 3 + 1) * DOUT + o;
    const float* p2 = g_P + ((size_t)(MFR + n * SEQF + f2) * 3 + 2) * DOUT + o;
    float4 v0 = *(const float4*)p0, v1 = *(const float4*)p1, v2 = *(const float4*)p2;
    float4 vb = *(const float4*)(bias + o);
    float4 r;
    r.x = fmaxf(v0.x + v1.x + v2.x + vb.x, 0.f);
    r.y = fmaxf(v0.y + v1.y + v2.y + vb.y, 0.f);
    r.z = fmaxf(v0.z + v1.z + v2.z + vb.z, 0.f);
    r.w = fmaxf(v0.w + v1.w + v2.w + vb.w, 0.f);
    uint2 p = pack_half4(r);
    *(uint2*)dst = p;
    float tot = block_reduce_sum(sumsq_half4(p));
    if (threadIdx.x == 0) g_s2[pcol] = tot;
}

// ---------------- stage 3: fused distance GEMM + segmented class min ----------------
__global__ void init_min()
{
    int i = blockIdx.x * blockDim.x + threadIdx.x;
    if (i < NWAY * QPAD) g_minbits[i] = 0x7F7FFFFFu;
}

__global__ __launch_bounds__(256, 1) void gemm3()
{
    extern __shared__ char smem[];
    __shared__ float s2s[128];
    __shared__ float rowmin[128][4][2];
    const int nBase = blockIdx.x * 128;          // packed support col base
    const int mBase = blockIdx.y * 128;
    const int tid = threadIdx.x, l = tid & 31;
    const int wm = (tid >> 5) >> 2, wn = (tid >> 5) & 3;

    if (tid < 128) s2s[tid] = g_s2[nBase + tid];

    float acc[4][4][4];
    #pragma unroll
    for (int a = 0; a < 4; a++)
        #pragma unroll
        for (int b = 0; b < 4; b++)
            #pragma unroll
            for (int d = 0; d < 4; d++) acc[a][b][d] = 0.f;

    mma_mainloop<DOUT / 128>(
        g_QE + (size_t)mBase * DOUT,
        g_SE + (size_t)nBase * DOUT,
        DOUT, smem, acc);

    // segmented epilogue: tile spans at most 2 classes (280 > 128, boundary even)
    const int cLo = min(nBase / SACT, NWAY - 1);
    const int cHi = min((nBase + 127) / SACT, NWAY - 1);
    float mnL0[4], mnL1[4], mnH0[4], mnH1[4];
    #pragma unroll
    for (int mi = 0; mi < 4; mi++) { mnL0[mi] = 3e38f; mnL1[mi] = 3e38f; mnH0[mi] = 3e38f; mnH1[mi] = 3e38f; }
    #pragma unroll
    for (int ni = 0; ni < 4; ni++) {
        const int col = wn * 32 + ni * 8 + (l & 3) * 2;
        const bool isHi = (min((nBase + col) / SACT, NWAY - 1) != cLo);
        const float sa = s2s[col], sbv = s2s[col + 1];
        #pragma unroll
        for (int mi = 0; mi < 4; mi++) {
            float v0 = fminf(fmaf(-2.f, acc[mi][ni][0], sa), fmaf(-2.f, acc[mi][ni][1], sbv));
            float v1 = fminf(fmaf(-2.f, acc[mi][ni][2], sa), fmaf(-2.f, acc[mi][ni][3], sbv));
            if (isHi) { mnH0[mi] = fminf(mnH0[mi], v0); mnH1[mi] = fminf(mnH1[mi], v1); }
            else      { mnL0[mi] = fminf(mnL0[mi], v0); mnL1[mi] = fminf(mnL1[mi], v1); }
        }
    }
    #pragma unroll
    for (int mi = 0; mi < 4; mi++) {
        #pragma unroll
        for (int s = 1; s <= 2; s <<= 1) {
            mnL0[mi] = fminf(mnL0[mi], __shfl_xor_sync(0xffffffffu, mnL0[mi], s));
            mnL1[mi] = fminf(mnL1[mi], __shfl_xor_sync(0xffffffffu, mnL1[mi], s));
            mnH0[mi] = fminf(mnH0[mi], __shfl_xor_sync(0xffffffffu, mnH0[mi], s));
            mnH1[mi] = fminf(mnH1[mi], __shfl_xor_sync(0xffffffffu, mnH1[mi], s));
        }
    }
    if ((l & 3) == 0) {
        #pragma unroll
        for (int mi = 0; mi < 4; mi++) {
            const int r0 = wm * 64 + mi * 16 + (l >> 2);
            rowmin[r0][wn][0] = mnL0[mi];      rowmin[r0][wn][1] = mnH0[mi];
            rowmin[r0 + 8][wn][0] = mnL1[mi];  rowmin[r0 + 8][wn][1] = mnH1[mi];
        }
    }
    __syncthreads();
    if (tid < 128) {
        float mL = fminf(fminf(rowmin[tid][0][0], rowmin[tid][1][0]),
                         fminf(rowmin[tid][2][0], rowmin[tid][3][0]));
        const float q2v = g_q2[mBase + tid];
        atomicMin(&g_minbits[cLo * QPAD + mBase + tid],
                  __float_as_uint(fmaxf(q2v + mL, 0.f)));
        if (cHi != cLo) {
            float mH = fminf(fminf(rowmin[tid][0][1], rowmin[tid][1][1]),
                             fminf(rowmin[tid][2][1], rowmin[tid][3][1]));
            atomicMin(&g_minbits[cHi * QPAD + mBase + tid],
                      __float_as_uint(fmaxf(q2v + mH, 0.f)));
        }
    }
}

// ---------------- stage 4: finalize ----------------
__global__ void finalize(float* __restrict__ out)
{
    int idx = blockIdx.x * blockDim.x + threadIdx.x;
    if (idx >= NQ * NWAY) return;
    int q = idx / NWAY, c = idx % NWAY;
    const unsigned* src = g_minbits + (size_t)c * QPAD + (size_t)q * TN;
    float s = 0.f;
    #pragma unroll 8
    for (int t = 0; t < TN; ++t) s += sqrtf(__uint_as_float(src[t]));
    out[q * NWAY + c] = -s * (1.0f / (float)TN);
}

// ---------------- launch ----------------
extern "C" void kernel_launch(void* const* d_in, const int* in_sizes, int n_in,
                              void* d_out, int out_size)
{
    const float* support = (const float*)d_in[0];      // [25,8,2048]
    const int*   labraw  = (const int*)d_in[1];        // [25] int32/int64
    const float* queries = (const float*)d_in[2];      // [400,8,2048]
    const float* W       = (const float*)d_in[3];      // [1024,6144]
    const float* bias    = (const float*)d_in[4];      // [1024]
    float*       out     = (float*)d_out;              // [400,5]
    (void)in_sizes; (void)n_in; (void)out_size;

    cudaFuncSetAttribute(gemm1, cudaFuncAttributeMaxDynamicSharedMemorySize, SMEM_BYTES);
    cudaFuncSetAttribute(gemm3, cudaFuncAttributeMaxDynamicSharedMemorySize, SMEM_BYTES);

    build_clsmap<<<1, 32>>>(labraw);

    convhalf<<<(MFR * DIM / 4 + 255) / 256, 256>>>(queries, 0, MFR * DIM / 4);
    convhalf<<<(NSUP * SEQF * DIM / 4 + 255) / 256, 256>>>(
        support, (size_t)MFR * DIM, NSUP * SEQF * DIM / 4);
    zfillA<<<((MPAD - MFRS) * DIM / 4 + 255) / 256, 256>>>();
    convW<<<(3 * DOUT * DIM / 4 + 255) / 256, 256>>>(W);

    gemm1<<<dim3(DOUT / 128, 3, MPAD / 128), 256, SMEM_BYTES>>>();

    assemble_q<<<QPAD, 256>>>(bias);
    assemble_s<<<SPACK, 256>>>(bias);

    init_min<<<(NWAY * QPAD + 255) / 256, 256>>>();
    gemm3<<<dim3(SPACK / 128, QPAD / 128), 256, SMEM_BYTES>>>();

    finalize<<<(NQ * NWAY + 255) / 256, 256>>>(out);
}